// round 1
// baseline (speedup 1.0000x reference)
#include <cuda_runtime.h>

#define BN 128
#define PN 24564
#define ON 20
#define CHUNKS 3
#define CHUNK ((PN + CHUNKS - 1) / CHUNKS)   // 8188
#define U3 8
#define THRESH 0.5f

// ---- scratch (static device globals; no allocation allowed) ----
__device__ unsigned long long g_bestprior[BN * ON];  // packed (iou_bits<<32)|(~p)
__device__ unsigned char     g_match[BN * PN];       // (best_truth_idx<<1) | pos
__device__ double            g_acc[3];               // loss_l, loss_c, num_pos

// ---------------------------------------------------------------- init
__global__ void k_init() {
    int i = blockIdx.x * blockDim.x + threadIdx.x;
    if (i < BN * ON) g_bestprior[i] = 0ULL;
    if (i < 3) g_acc[i] = 0.0;
}

// ---------------------------------------------------------------- matching
__global__ __launch_bounds__(256, 2)
void k_match(const float4* __restrict__ priors, const float* __restrict__ gt) {
    __shared__ float4 sbox[ON];
    __shared__ float  sarea[ON];
    __shared__ unsigned long long red[ON][256];

    const int b   = blockIdx.y;
    const int tid = threadIdx.x;

    if (tid < ON) {
        const float* g = gt + (b * ON + tid) * 5;
        float4 v = make_float4(g[0], g[1], g[2], g[3]);
        sbox[tid]  = v;
        sarea[tid] = (v.z - v.x) * (v.w - v.y);
    }
    __syncthreads();

    float bo[ON];   // best iou per GT (this thread)
    int   bp[ON];   // prior index at that best
#pragma unroll
    for (int o = 0; o < ON; o++) { bo[o] = -1.0f; bp[o] = 0; }

    const int p0 = blockIdx.x * CHUNK;
    const int p1 = (p0 + CHUNK < PN) ? (p0 + CHUNK) : PN;

    for (int p = p0 + tid; p < p1; p += 256) {
        float4 pr = __ldg(&priors[p]);
        float hx = pr.z * 0.5f, hy = pr.w * 0.5f;
        float px0 = pr.x - hx, py0 = pr.y - hy;
        float px1 = pr.x + hx, py1 = pr.y + hy;
        float ap  = (px1 - px0) * (py1 - py0);   // mirror reference (corner-form area)

        float maxv = -1.0f; int maxo = 0;
#pragma unroll
        for (int o = 0; o < ON; o++) {
            float4 t = sbox[o];
            float ltx = fmaxf(t.x, px0), lty = fmaxf(t.y, py0);
            float rbx = fminf(t.z, px1), rby = fminf(t.w, py1);
            float w = fmaxf(rbx - ltx, 0.0f);
            float h = fmaxf(rby - lty, 0.0f);
            float inter = w * h;
            float iou = __fdividef(inter, sarea[o] + ap - inter);
            if (iou > maxv) { maxv = iou; maxo = o; }   // strict > : first-o wins (jnp.argmax)
            if (iou > bo[o]) { bo[o] = iou; bp[o] = p; } // strict > : smallest-p wins in-thread
        }
        g_match[b * PN + p] = (unsigned char)((maxo << 1) | (maxv >= THRESH ? 1 : 0));
    }

    // pack and tree-reduce per-o best over the block; larger packed = higher iou,
    // tie -> larger ~p = smaller p (matches jnp.argmax first-index).
#pragma unroll
    for (int o = 0; o < ON; o++) {
        unsigned int hv = __float_as_uint(fmaxf(bo[o], 0.0f));
        red[o][tid] = ((unsigned long long)hv << 32)
                    | (unsigned long long)(0xFFFFFFFFu - (unsigned)bp[o]);
    }
    __syncthreads();
    for (int s = 128; s > 0; s >>= 1) {
        if (tid < s) {
#pragma unroll
            for (int o = 0; o < ON; o++) {
                unsigned long long a = red[o][tid];
                unsigned long long c = red[o][tid + s];
                if (c > a) red[o][tid] = c;
            }
        }
        __syncthreads();
    }
    if (tid < ON) atomicMax(&g_bestprior[b * ON + tid], red[tid][0]);
}

// ---------------------------------------------------------------- override
// Sequential o-loop per image => last-o-wins scatter (mirrors .at[].set order).
__global__ void k_override() {
    int b = threadIdx.x;
    if (b < BN) {
        for (int o = 0; o < ON; o++) {
            unsigned long long pk = g_bestprior[b * ON + o];
            unsigned int p = 0xFFFFFFFFu - (unsigned int)(pk & 0xFFFFFFFFull);
            g_match[b * PN + p] = (unsigned char)((o << 1) | 1);
        }
    }
}

// ---------------------------------------------------------------- losses
__device__ __forceinline__ float smooth_l1(float d) {
    float ad = fabsf(d);
    return (ad < 1.0f) ? 0.5f * d * d : ad - 0.5f;
}

__global__ __launch_bounds__(256)
void k_loss(const float4* __restrict__ loc, const float2* __restrict__ conf,
            const float4* __restrict__ priors, const float* __restrict__ gt) {
    __shared__ float4 sbox[ON];
    __shared__ int    slab[ON];
    __shared__ float  swl[8], swc[8];
    __shared__ int    swn[8];

    const int b   = blockIdx.y;
    const int tid = threadIdx.x;

    if (tid < ON) {
        const float* g = gt + (b * ON + tid) * 5;
        sbox[tid] = make_float4(g[0], g[1], g[2], g[3]);
        slab[tid] = (int)g[4];
    }
    __syncthreads();

    float sl = 0.0f, sc = 0.0f; int cnt = 0;
    const int base = blockIdx.x * (256 * U3) + tid;

    for (int u = 0; u < U3; u++) {
        int p = base + u * 256;
        if (p >= PN) break;
        int ix = b * PN + p;
        unsigned char code = g_match[ix];
        int pos = code & 1;
        int idx = code >> 1;

        // focal loss (pos_neg mask is always true: conf_t in {0,1})
        float2 cd = __ldg(&conf[ix]);
        int cls = pos ? (slab[idx] + 1) : 0;
        float m  = fmaxf(cd.x, cd.y);
        float e0 = __expf(cd.x - m), e1 = __expf(cd.y - m);
        float inv = __fdividef(1.0f, e0 + e1);
        float pc = (cls == 1) ? e1 * inv : e0 * inv;
        pc = fminf(fmaxf(pc, 1e-7f), 1.0f - 1e-7f);
        float om = 1.0f - pc;
        float fl = 0.25f * (-__logf(pc)) * om * om;
        if (cls < 2) sc += fl;   // one_hot(conf_t>=2, 2) == 0

        // smooth-L1 on positives only (predicated loads save DRAM lines)
        if (pos) {
            cnt++;
            float4 ld = __ldg(&loc[ix]);
            float4 pr = __ldg(&priors[p]);
            float4 mb = sbox[idx];
            float iw = __fdividef(1.0f, pr.z);
            float ih = __fdividef(1.0f, pr.w);
            float gx = ((mb.x + mb.z) * 0.5f - pr.x) * 10.0f * iw;
            float gy = ((mb.y + mb.w) * 0.5f - pr.y) * 10.0f * ih;
            float gw = __logf((mb.z - mb.x) * iw) * 5.0f;
            float gh = __logf((mb.w - mb.y) * ih) * 5.0f;
            sl += smooth_l1(ld.x - gx);
            sl += smooth_l1(ld.y - gy);
            sl += smooth_l1(ld.z - gw);
            sl += smooth_l1(ld.w - gh);
        }
    }

    // warp -> block -> global (double) reduction
#pragma unroll
    for (int off = 16; off; off >>= 1) {
        sl  += __shfl_down_sync(0xFFFFFFFFu, sl, off);
        sc  += __shfl_down_sync(0xFFFFFFFFu, sc, off);
        cnt += __shfl_down_sync(0xFFFFFFFFu, cnt, off);
    }
    int wid = tid >> 5, lid = tid & 31;
    if (lid == 0) { swl[wid] = sl; swc[wid] = sc; swn[wid] = cnt; }
    __syncthreads();
    if (tid == 0) {
        float tl = 0.0f, tc = 0.0f; int tn = 0;
#pragma unroll
        for (int w = 0; w < 8; w++) { tl += swl[w]; tc += swc[w]; tn += swn[w]; }
        atomicAdd(&g_acc[0], (double)tl);
        atomicAdd(&g_acc[1], (double)tc);
        atomicAdd(&g_acc[2], (double)tn);
    }
}

// ---------------------------------------------------------------- finalize
__global__ void k_final(float* out) {
    double np = g_acc[2];
    if (np < 1.0) np = 1.0;
    out[0] = (float)(g_acc[0] / np);
    out[1] = (float)(g_acc[1] / np);
}

// ---------------------------------------------------------------- launch
extern "C" void kernel_launch(void* const* d_in, const int* in_sizes, int n_in,
                              void* d_out, int out_size) {
    const float4* loc    = (const float4*)d_in[0];  // [B,P,4] f32
    const float2* conf   = (const float2*)d_in[1];  // [B,P,2] f32
    const float4* priors = (const float4*)d_in[2];  // [P,4]   f32
    const float*  gt     = (const float*)d_in[3];   // [B,O,5] f32

    k_init<<<(BN * ON + 255) / 256, 256>>>();

    dim3 g1(CHUNKS, BN);
    k_match<<<g1, 256>>>(priors, gt);

    k_override<<<1, 128>>>();

    dim3 g3((PN + 256 * U3 - 1) / (256 * U3), BN);
    k_loss<<<g3, 256>>>(loc, conf, priors, gt);

    k_final<<<1, 1>>>((float*)d_out);
}